// round 2
// baseline (speedup 1.0000x reference)
#include <cuda_runtime.h>
#include <math.h>

// ---------------------------------------------------------------------------
// Problem constants (fixed shapes from reference)
// ---------------------------------------------------------------------------
#define BSZ    4
#define SEQ    2048
#define DIM    1024
#define EDIM   2048          // d_inner
#define NSTATE 16
#define KCONV  4
#define DTR    64            // dt_rank
#define HDIM   4096
#define ROWS   (BSZ*SEQ)     // 8192 token rows
#define PROJC  (DTR + 2*NSTATE)   // 96

// ---------------------------------------------------------------------------
// Scratch (device globals; no allocation allowed in kernel_launch)
// ---------------------------------------------------------------------------
__device__ float g_xz  [ROWS * 2 * EDIM];   // 8192 x 4096
__device__ float g_xc  [ROWS * EDIM];       // conv+silu output
__device__ float g_dtBC[ROWS * PROJC];      // [dt(64) | B(16) | C(16)]
__device__ float g_dt  [ROWS * EDIM];       // softplus(dt)
__device__ float g_y   [ROWS * EDIM];       // gated scan output
__device__ float g_h   [ROWS * DIM];        // x + mamba_out
__device__ float g_hn  [ROWS * DIM];        // layernorm output
__device__ float g_mid [ROWS * HDIM];       // gelu(hn@W1+b1)
__device__ float g_A   [EDIM * NSTATE];     // -exp(A_log)

// ===========================================================================
// TF32 tensor-core GEMM via mma.sync.m16n8k8 (row.col, f32 accum).
// C[M,N] = epi( A[M,K] @ B[K,N] ), row-major A and B.
// BM=BN=128, BK=16, 256 threads = 8 warps as 2(M) x 4(N); each warp owns
// a 64x32 tile = 4x4 m16n8k8 tiles. Requires M%128==0, N%128==0, K%16==0.
// EPI: 0=store  2=+res  3=bias+gelu(erf)  4=bias
// ===========================================================================
#define TBM 128
#define TBN 128
#define TBK 16
#define TPITCH (TBM + 8)     // 136 floats: row-to-row bank shift of 8 -> conflict-free frags

__device__ __forceinline__ unsigned f2tf32(float x) {
    unsigned y;
    asm("cvt.rna.tf32.f32 %0, %1;" : "=r"(y) : "f"(x));
    return y;
}

template<int EPI>
__global__ __launch_bounds__(256) void tgemm_k(
    const float* __restrict__ A, const float* __restrict__ B, float* __restrict__ C,
    int Kdim, int lda, int ldb, int ldc,
    const float* __restrict__ bias, const float* __restrict__ res, int ldres)
{
    __shared__ unsigned As[TBK][TPITCH];   // As[k][m], tf32 bit patterns
    __shared__ unsigned Bs[TBK][TPITCH];   // Bs[k][n]

    const int tid  = threadIdx.x;
    const int warp = tid >> 5;
    const int lane = tid & 31;
    const int gid  = lane >> 2;     // 0..7
    const int tig  = lane & 3;      // 0..3
    const int wm   = (warp & 1) * 64;    // warp M offset within CTA tile
    const int wn   = (warp >> 1) * 32;   // warp N offset within CTA tile
    const int blockM = blockIdx.y * TBM;
    const int blockN = blockIdx.x * TBN;

    float acc[4][4][4];
    #pragma unroll
    for (int mt = 0; mt < 4; mt++)
        #pragma unroll
        for (int nt = 0; nt < 4; nt++)
            #pragma unroll
            for (int i = 0; i < 4; i++) acc[mt][nt][i] = 0.f;

    // Staging-load indices
    const int aRow = tid >> 1;            // 0..127
    const int aC0  = (tid & 1) * 8;       // 0 or 8; two float4 at aC0, aC0+4
    const int bRow = tid >> 4;            // 0..15
    const int bC0  = (tid & 15) * 4;      // 0..60; two float4 at bC0, bC0+64

    const float* Ap = A + (size_t)(blockM + aRow) * lda;
    const float* Bp = B + (size_t)bRow * ldb + blockN;

    for (int k0 = 0; k0 < Kdim; k0 += TBK) {
        const float4 av0 = *reinterpret_cast<const float4*>(Ap + k0 + aC0);
        const float4 av1 = *reinterpret_cast<const float4*>(Ap + k0 + aC0 + 4);
        const float4 bv0 = *reinterpret_cast<const float4*>(Bp + (size_t)k0 * ldb + bC0);
        const float4 bv1 = *reinterpret_cast<const float4*>(Bp + (size_t)k0 * ldb + bC0 + 64);

        As[aC0 + 0][aRow] = f2tf32(av0.x);
        As[aC0 + 1][aRow] = f2tf32(av0.y);
        As[aC0 + 2][aRow] = f2tf32(av0.z);
        As[aC0 + 3][aRow] = f2tf32(av0.w);
        As[aC0 + 4][aRow] = f2tf32(av1.x);
        As[aC0 + 5][aRow] = f2tf32(av1.y);
        As[aC0 + 6][aRow] = f2tf32(av1.z);
        As[aC0 + 7][aRow] = f2tf32(av1.w);

        Bs[bRow][bC0 + 0]  = f2tf32(bv0.x);
        Bs[bRow][bC0 + 1]  = f2tf32(bv0.y);
        Bs[bRow][bC0 + 2]  = f2tf32(bv0.z);
        Bs[bRow][bC0 + 3]  = f2tf32(bv0.w);
        Bs[bRow][bC0 + 64] = f2tf32(bv1.x);
        Bs[bRow][bC0 + 65] = f2tf32(bv1.y);
        Bs[bRow][bC0 + 66] = f2tf32(bv1.z);
        Bs[bRow][bC0 + 67] = f2tf32(bv1.w);
        __syncthreads();

        #pragma unroll
        for (int ks = 0; ks < 2; ks++) {
            const int kb = ks * 8;
            unsigned af[4][4], bf[4][2];
            #pragma unroll
            for (int mt = 0; mt < 4; mt++) {
                const int m = wm + mt * 16;
                af[mt][0] = As[kb + tig    ][m + gid];
                af[mt][1] = As[kb + tig    ][m + gid + 8];
                af[mt][2] = As[kb + tig + 4][m + gid];
                af[mt][3] = As[kb + tig + 4][m + gid + 8];
            }
            #pragma unroll
            for (int nt = 0; nt < 4; nt++) {
                const int n = wn + nt * 8;
                bf[nt][0] = Bs[kb + tig    ][n + gid];
                bf[nt][1] = Bs[kb + tig + 4][n + gid];
            }
            #pragma unroll
            for (int mt = 0; mt < 4; mt++)
                #pragma unroll
                for (int nt = 0; nt < 4; nt++) {
                    asm volatile(
                        "mma.sync.aligned.m16n8k8.row.col.f32.tf32.tf32.f32 "
                        "{%0,%1,%2,%3}, {%4,%5,%6,%7}, {%8,%9}, {%0,%1,%2,%3};"
                        : "+f"(acc[mt][nt][0]), "+f"(acc[mt][nt][1]),
                          "+f"(acc[mt][nt][2]), "+f"(acc[mt][nt][3])
                        : "r"(af[mt][0]), "r"(af[mt][1]), "r"(af[mt][2]), "r"(af[mt][3]),
                          "r"(bf[nt][0]), "r"(bf[nt][1]));
                }
        }
        __syncthreads();
    }

    // Epilogue. c0:(gid, 2*tig) c1:(gid, 2*tig+1) c2:(gid+8, 2*tig) c3:(gid+8, 2*tig+1)
    #pragma unroll
    for (int mt = 0; mt < 4; mt++) {
        #pragma unroll
        for (int nt = 0; nt < 4; nt++) {
            const int r0 = blockM + wm + mt * 16 + gid;
            const int c0 = blockN + wn + nt * 8 + 2 * tig;
            #pragma unroll
            for (int half = 0; half < 2; half++) {
                const int r = r0 + half * 8;
                #pragma unroll
                for (int j = 0; j < 2; j++) {
                    const int c = c0 + j;
                    float v = acc[mt][nt][half * 2 + j];
                    if (EPI == 2) {
                        v += res[(size_t)r * ldres + c];
                    } else if (EPI == 3) {
                        v += bias[c];
                        v = 0.5f * v * (1.f + erff(v * 0.70710678118654752f));
                    } else if (EPI == 4) {
                        v += bias[c];
                    }
                    C[(size_t)r * ldc + c] = v;
                }
            }
        }
    }
}

// ---------------------------------------------------------------------------
// Fallback fp32 tiled GEMM (used for the small / precision-critical GEMMs).
// BM=BN=128, BK=8, 256 threads, 8x8 per thread as 2x2 blocks of 4x4.
// EPI: 0=store  1=bias+softplus
// ---------------------------------------------------------------------------
#define BM 128
#define BN 128
#define BK 8

template<int EPI>
__global__ __launch_bounds__(256) void sgemm_k(
    const float* __restrict__ A, const float* __restrict__ B, float* __restrict__ C,
    int M, int Ncol, int Kdim, int lda, int ldb, int ldc,
    const float* __restrict__ bias)
{
    __shared__ float As[BK][BM + 4];
    __shared__ float Bs[BK][BN + 4];

    const int tid = threadIdx.x;
    const int tx  = tid & 15;
    const int ty  = tid >> 4;
    const int aRow = tid >> 1;
    const int aCol = (tid & 1) << 2;
    const int bRow = tid >> 5;
    const int bCol = (tid & 31) << 2;
    const int blockM = blockIdx.y * BM;
    const int blockN = blockIdx.x * BN;

    float acc[2][2][4][4];
    #pragma unroll
    for (int p = 0; p < 2; p++)
        #pragma unroll
        for (int q = 0; q < 2; q++)
            #pragma unroll
            for (int i = 0; i < 4; i++)
                #pragma unroll
                for (int j = 0; j < 4; j++) acc[p][q][i][j] = 0.f;

    const float* Ap = A + (size_t)(blockM + aRow) * lda + aCol;
    const float* Bp = B + (size_t)bRow * ldb + blockN + bCol;
    const bool bIn = (blockN + bCol) < Ncol;

    for (int k0 = 0; k0 < Kdim; k0 += BK) {
        float4 av = *reinterpret_cast<const float4*>(Ap + k0);
        float4 bv = make_float4(0.f, 0.f, 0.f, 0.f);
        if (bIn) bv = *reinterpret_cast<const float4*>(Bp + (size_t)k0 * ldb);
        As[aCol + 0][aRow] = av.x;
        As[aCol + 1][aRow] = av.y;
        As[aCol + 2][aRow] = av.z;
        As[aCol + 3][aRow] = av.w;
        *reinterpret_cast<float4*>(&Bs[bRow][bCol]) = bv;
        __syncthreads();

        #pragma unroll
        for (int kk = 0; kk < BK; kk++) {
            float ar[2][4], br[2][4];
            #pragma unroll
            for (int p = 0; p < 2; p++) {
                float4 t = *reinterpret_cast<const float4*>(&As[kk][p * 64 + ty * 4]);
                ar[p][0] = t.x; ar[p][1] = t.y; ar[p][2] = t.z; ar[p][3] = t.w;
                float4 u = *reinterpret_cast<const float4*>(&Bs[kk][p * 64 + tx * 4]);
                br[p][0] = u.x; br[p][1] = u.y; br[p][2] = u.z; br[p][3] = u.w;
            }
            #pragma unroll
            for (int p = 0; p < 2; p++)
                #pragma unroll
                for (int q = 0; q < 2; q++)
                    #pragma unroll
                    for (int i = 0; i < 4; i++)
                        #pragma unroll
                        for (int j = 0; j < 4; j++)
                            acc[p][q][i][j] = fmaf(ar[p][i], br[q][j], acc[p][q][i][j]);
        }
        __syncthreads();
    }

    #pragma unroll
    for (int p = 0; p < 2; p++) {
        #pragma unroll
        for (int i = 0; i < 4; i++) {
            const int r = blockM + p * 64 + ty * 4 + i;
            #pragma unroll
            for (int q = 0; q < 2; q++) {
                const int cbase = blockN + q * 64 + tx * 4;
                if (cbase < Ncol) {
                    #pragma unroll
                    for (int j = 0; j < 4; j++) {
                        const int c = cbase + j;
                        float v = acc[p][q][i][j];
                        if (EPI == 1) {
                            v += bias[c];
                            v = (v > 20.f) ? v : log1pf(expf(v));
                        }
                        C[(size_t)r * ldc + c] = v;
                    }
                }
            }
        }
    }
}

// ---------------------------------------------------------------------------
// Depthwise causal conv1d (K=4) + silu. xp = g_xz[:, 0:EDIM]  ->  g_xc
// ---------------------------------------------------------------------------
__global__ __launch_bounds__(256) void conv_silu_k(
    const float* __restrict__ cw, const float* __restrict__ cb)
{
    const int idx = blockIdx.x * blockDim.x + threadIdx.x;
    if (idx >= ROWS * EDIM) return;
    const int e   = idx & (EDIM - 1);
    const int row = idx >> 11;
    const int l   = row & (SEQ - 1);

    const float w0 = cw[e * 4 + 0], w1 = cw[e * 4 + 1];
    const float w2 = cw[e * 4 + 2], w3 = cw[e * 4 + 3];
    const float* base = g_xz + (size_t)row * (2 * EDIM) + e;

    float acc = fmaf(w3, base[0], cb[e]);
    if (l >= 1) acc = fmaf(w2, base[-(ptrdiff_t)(2 * EDIM)], acc);
    if (l >= 2) acc = fmaf(w1, base[-(ptrdiff_t)(4 * EDIM)], acc);
    if (l >= 3) acc = fmaf(w0, base[-(ptrdiff_t)(6 * EDIM)], acc);
    acc = acc / (1.f + expf(-acc));          // silu
    g_xc[idx] = acc;
}

// ---------------------------------------------------------------------------
// A = -exp(A_log)
// ---------------------------------------------------------------------------
__global__ void prep_A_k(const float* __restrict__ A_log)
{
    const int i = blockIdx.x * blockDim.x + threadIdx.x;
    if (i < EDIM * NSTATE) g_A[i] = -expf(A_log[i]);
}

// ---------------------------------------------------------------------------
// Selective scan. One state n per lane; 16-lane group = one (b,e) sequence;
// 2 sequences per warp; 16 sequences per block (256 thr); 512 blocks.
// Fuses: y = (scan + u*D) * silu(z)   ->   g_y
// ---------------------------------------------------------------------------
__global__ __launch_bounds__(256) void scan_k(const float* __restrict__ Dp)
{
    const int g = threadIdx.x >> 4;
    const int n = threadIdx.x & 15;
    const int s = blockIdx.x * 16 + g;       // 0..8191
    const int b = s >> 11;                   // / EDIM
    const int e = s & (EDIM - 1);

    const float An = g_A[e * NSTATE + n];
    const float De = Dp[e];
    float h = 0.f;

    const size_t row0 = (size_t)b * SEQ;
    const float* dt_e = g_dt + e;
    const float* xc_e = g_xc + e;
    const float* z_e  = g_xz + EDIM + e;
    float*       y_e  = g_y  + e;
    const float* bcB  = g_dtBC + DTR + n;
    const float* bcC  = g_dtBC + DTR + NSTATE + n;

    #pragma unroll 2
    for (int l = 0; l < SEQ; ++l) {
        const size_t r = row0 + l;
        const float du = dt_e[r * EDIM];
        const float u  = xc_e[r * EDIM];
        const float Bn = bcB[r * PROJC];
        const float Cn = bcC[r * PROJC];

        const float a = __expf(du * An);
        h = fmaf(a, h, du * u * Bn);

        float p = h * Cn;
        p += __shfl_xor_sync(0xffffffffu, p, 1);
        p += __shfl_xor_sync(0xffffffffu, p, 2);
        p += __shfl_xor_sync(0xffffffffu, p, 4);
        p += __shfl_xor_sync(0xffffffffu, p, 8);

        if (n == 0) {
            const float z  = z_e[r * (2 * EDIM)];
            const float sz = z / (1.f + __expf(-z));
            y_e[r * EDIM]  = fmaf(u, De, p) * sz;
        }
    }
}

// ---------------------------------------------------------------------------
// LayerNorm over DIM=1024: g_h -> g_hn. 256 threads/row, float4 per thread.
// ---------------------------------------------------------------------------
__global__ __launch_bounds__(256) void ln_k(
    const float* __restrict__ w, const float* __restrict__ b)
{
    const int row = blockIdx.x;
    const float4 v = reinterpret_cast<const float4*>(g_h + (size_t)row * DIM)[threadIdx.x];

    float s  = v.x + v.y + v.z + v.w;
    float ss = v.x * v.x + v.y * v.y + v.z * v.z + v.w * v.w;
    #pragma unroll
    for (int o = 16; o > 0; o >>= 1) {
        s  += __shfl_xor_sync(0xffffffffu, s,  o);
        ss += __shfl_xor_sync(0xffffffffu, ss, o);
    }
    __shared__ float sh_s[8], sh_ss[8];
    const int warp = threadIdx.x >> 5, lane = threadIdx.x & 31;
    if (lane == 0) { sh_s[warp] = s; sh_ss[warp] = ss; }
    __syncthreads();
    if (warp == 0) {
        s  = (lane < 8) ? sh_s[lane]  : 0.f;
        ss = (lane < 8) ? sh_ss[lane] : 0.f;
        #pragma unroll
        for (int o = 4; o > 0; o >>= 1) {
            s  += __shfl_xor_sync(0xffffffffu, s,  o);
            ss += __shfl_xor_sync(0xffffffffu, ss, o);
        }
        if (lane == 0) { sh_s[0] = s; sh_ss[0] = ss; }
    }
    __syncthreads();
    const float mean = sh_s[0] * (1.f / DIM);
    const float var  = sh_ss[0] * (1.f / DIM) - mean * mean;
    const float inv  = rsqrtf(var + 1e-5f);

    const float4 wv = reinterpret_cast<const float4*>(w)[threadIdx.x];
    const float4 bv = reinterpret_cast<const float4*>(b)[threadIdx.x];
    float4 o;
    o.x = (v.x - mean) * inv * wv.x + bv.x;
    o.y = (v.y - mean) * inv * wv.y + bv.y;
    o.z = (v.z - mean) * inv * wv.z + bv.z;
    o.w = (v.w - mean) * inv * wv.w + bv.w;
    reinterpret_cast<float4*>(g_hn + (size_t)row * DIM)[threadIdx.x] = o;
}

// ---------------------------------------------------------------------------
// Launch
// ---------------------------------------------------------------------------
extern "C" void kernel_launch(void* const* d_in, const int* in_sizes, int n_in,
                              void* d_out, int out_size)
{
    const float* x       = (const float*)d_in[0];
    const float* W_in    = (const float*)d_in[1];
    const float* conv_w  = (const float*)d_in[2];
    const float* conv_b  = (const float*)d_in[3];
    const float* W_xproj = (const float*)d_in[4];
    const float* W_dt    = (const float*)d_in[5];
    const float* b_dt    = (const float*)d_in[6];
    const float* A_log   = (const float*)d_in[7];
    const float* D_param = (const float*)d_in[8];
    const float* W_out   = (const float*)d_in[9];
    const float* ln_w    = (const float*)d_in[10];
    const float* ln_b    = (const float*)d_in[11];
    const float* W1      = (const float*)d_in[12];
    const float* b1      = (const float*)d_in[13];
    const float* W2      = (const float*)d_in[14];
    const float* b2      = (const float*)d_in[15];
    float* out = (float*)d_out;

    float *xz, *xc, *dtbc, *dtb, *yb, *hb, *hnb, *midb;
    cudaGetSymbolAddress((void**)&xz,   g_xz);
    cudaGetSymbolAddress((void**)&xc,   g_xc);
    cudaGetSymbolAddress((void**)&dtbc, g_dtBC);
    cudaGetSymbolAddress((void**)&dtb,  g_dt);
    cudaGetSymbolAddress((void**)&yb,   g_y);
    cudaGetSymbolAddress((void**)&hb,   g_h);
    cudaGetSymbolAddress((void**)&hnb,  g_hn);
    cudaGetSymbolAddress((void**)&midb, g_mid);

    // 0) A = -exp(A_log)
    prep_A_k<<<(EDIM * NSTATE + 255) / 256, 256>>>(A_log);

    // 1) xz = x @ W_in                      (8192 x 4096, K=1024)   [tf32]
    tgemm_k<0><<<dim3(4096 / TBN, ROWS / TBM), 256>>>(
        x, W_in, xz, DIM, DIM, 4096, 4096, nullptr, nullptr, 0);

    // 2) depthwise causal conv + silu -> xc
    conv_silu_k<<<(ROWS * EDIM + 255) / 256, 256>>>(conv_w, conv_b);

    // 3) proj = xc @ W_xproj                (8192 x 96, K=2048)     [fp32]
    sgemm_k<0><<<dim3(1, ROWS / BM), 256>>>(
        xc, W_xproj, dtbc, ROWS, PROJC, EDIM, EDIM, PROJC, PROJC, nullptr);

    // 4) dt = softplus(proj[:, :64] @ W_dt + b_dt)  (8192x2048,K=64) [fp32]
    sgemm_k<1><<<dim3(EDIM / BN, ROWS / BM), 256>>>(
        dtbc, W_dt, dtb, ROWS, EDIM, DTR, PROJC, EDIM, EDIM, b_dt);

    // 5) selective scan (fused D-term + z gate)  -> g_y
    scan_k<<<512, 256>>>(D_param);

    // 6) h = x + y @ W_out                  (8192 x 1024, K=2048)   [tf32]
    tgemm_k<2><<<dim3(DIM / TBN, ROWS / TBM), 256>>>(
        yb, W_out, hb, EDIM, EDIM, DIM, DIM, nullptr, x, DIM);

    // 7) layernorm -> hn
    ln_k<<<ROWS, 256>>>(ln_w, ln_b);

    // 8) mid = gelu(hn @ W1 + b1)           (8192 x 4096, K=1024)   [tf32]
    tgemm_k<3><<<dim3(HDIM / TBN, ROWS / TBM), 256>>>(
        hnb, W1, midb, DIM, DIM, HDIM, HDIM, b1, nullptr, 0);

    // 9) out = mid @ W2 + b2                (8192 x 1024, K=4096)   [tf32]
    tgemm_k<4><<<dim3(DIM / TBN, ROWS / TBM), 256>>>(
        midb, W2, out, HDIM, HDIM, DIM, DIM, b2, nullptr, 0);
}

// round 3
// speedup vs baseline: 1.6251x; 1.6251x over previous
#include <cuda_runtime.h>
#include <math.h>

// ---------------------------------------------------------------------------
// Problem constants
// ---------------------------------------------------------------------------
#define BSZ    4
#define SEQ    2048
#define DIM    1024
#define EDIM   2048
#define NSTATE 16
#define DTR    64
#define HDIM   4096
#define ROWS   (BSZ*SEQ)          // 8192
#define PROJC  (DTR + 2*NSTATE)   // 96
#define KSPLIT 8                  // split-K factor for xproj

// ---------------------------------------------------------------------------
// Scratch (device globals)
// ---------------------------------------------------------------------------
__device__ float g_xz   [ROWS * 2 * EDIM];
__device__ float g_xc   [ROWS * EDIM];
__device__ float g_dtBC [ROWS * PROJC];
__device__ float g_dt   [ROWS * EDIM];
__device__ float g_y    [ROWS * EDIM];        // tf32-rounded
__device__ float g_h    [ROWS * DIM];
__device__ float g_hn   [ROWS * DIM];         // tf32-rounded
__device__ float g_mid  [ROWS * HDIM];        // tf32-rounded
__device__ float g_A    [EDIM * NSTATE];
__device__ float g_xpart[KSPLIT * ROWS * PROJC];
// tf32-rounded operand copies
__device__ float g_xr   [ROWS * DIM];
__device__ float g_Winr [DIM * 2 * EDIM];
__device__ float g_W1r  [DIM * HDIM];
__device__ float g_W2r  [HDIM * DIM];
__device__ float g_Woutr[EDIM * DIM];

__device__ __forceinline__ unsigned f2tf32(float x) {
    unsigned y;
    asm("cvt.rna.tf32.f32 %0, %1;" : "=r"(y) : "f"(x));
    return y;
}
__device__ __forceinline__ float roundtf(float x) { return __uint_as_float(f2tf32(x)); }

__device__ __forceinline__ void cp16(void* s, const void* g) {
    unsigned a = (unsigned)__cvta_generic_to_shared(s);
    asm volatile("cp.async.cg.shared.global [%0], [%1], 16;\n" :: "r"(a), "l"(g) : "memory");
}

// ---------------------------------------------------------------------------
// tf32 round-copy (weights + x), float4 grid-stride
// ---------------------------------------------------------------------------
__global__ void round_copy_k(const float* __restrict__ in, float* __restrict__ out, int n4)
{
    const int i = blockIdx.x * blockDim.x + threadIdx.x;
    if (i < n4) {
        float4 v = reinterpret_cast<const float4*>(in)[i];
        v.x = roundtf(v.x); v.y = roundtf(v.y); v.z = roundtf(v.z); v.w = roundtf(v.w);
        reinterpret_cast<float4*>(out)[i] = v;
    }
}

// ===========================================================================
// TF32 tensor-core GEMM, cp.async double-buffered.
// C[M,N] = epi( A[M,K] @ B[K,N] ), A/B row-major, operands pre-rounded tf32.
// BM=BN=128, BK=16, 256 thr = 8 warps (2M x 4N), warp tile 64x32 (4x4 mma).
// Requires M%128==0, N%128==0, K%16==0, lda/ldb/ldc %4==0.
// EPI: 0=store  2=+res  3=bias+gelu(erf)+tf32round  4=bias
// ===========================================================================
#define TBM 128
#define TBN 128
#define TBK 16
#define APITCH 20    // As[m][k] pitch: conflict-free frag loads, rows 16B-aligned
#define BPITCH 136   // Bs[k][n] pitch

template<int EPI>
__global__ __launch_bounds__(256) void tgemm_k(
    const float* __restrict__ A, const float* __restrict__ B, float* __restrict__ C,
    int Kdim, int lda, int ldb, int ldc,
    const float* __restrict__ bias, const float* __restrict__ res, int ldres)
{
    __shared__ float As[2][TBM][APITCH];
    __shared__ float Bs[2][TBK][BPITCH];

    const int tid  = threadIdx.x;
    const int warp = tid >> 5;
    const int lane = tid & 31;
    const int gid  = lane >> 2;
    const int tig  = lane & 3;
    const int wm   = (warp & 1) * 64;
    const int wn   = (warp >> 1) * 32;
    const int blockM = blockIdx.y * TBM;
    const int blockN = blockIdx.x * TBN;

    float acc[4][4][4];
    #pragma unroll
    for (int mt = 0; mt < 4; mt++)
        #pragma unroll
        for (int nt = 0; nt < 4; nt++)
            #pragma unroll
            for (int i = 0; i < 4; i++) acc[mt][nt][i] = 0.f;

    // copy mapping: A tile 128 rows x 16 k (2x16B per thread, same row)
    const int aRow = tid >> 1;
    const int aOff = (tid & 1) * 8;
    // B tile 16 k-rows x 128 n (2x16B per thread, same row)
    const int bRow = tid >> 4;
    const int bOff = (tid & 15) * 8;

    const float* Agp = A + (size_t)(blockM + aRow) * lda + aOff;
    const float* Bgp = B + (size_t)bRow * ldb + blockN + bOff;

    const int nch = Kdim / TBK;

    // preload chunk 0 into buffer 0
    cp16(&As[0][aRow][aOff],     Agp);
    cp16(&As[0][aRow][aOff + 4], Agp + 4);
    cp16(&Bs[0][bRow][bOff],     Bgp);
    cp16(&Bs[0][bRow][bOff + 4], Bgp + 4);
    asm volatile("cp.async.commit_group;\n" ::: "memory");

    for (int ch = 0; ch < nch; ch++) {
        const int buf = ch & 1;
        if (ch + 1 < nch) {
            const int k1 = (ch + 1) * TBK;
            cp16(&As[buf ^ 1][aRow][aOff],     Agp + k1);
            cp16(&As[buf ^ 1][aRow][aOff + 4], Agp + k1 + 4);
            cp16(&Bs[buf ^ 1][bRow][bOff],     Bgp + (size_t)k1 * ldb);
            cp16(&Bs[buf ^ 1][bRow][bOff + 4], Bgp + (size_t)k1 * ldb + 4);
            asm volatile("cp.async.commit_group;\n" ::: "memory");
            asm volatile("cp.async.wait_group 1;\n" ::: "memory");
        } else {
            asm volatile("cp.async.wait_group 0;\n" ::: "memory");
        }
        __syncthreads();

        #pragma unroll
        for (int ks = 0; ks < 2; ks++) {
            const int kb = ks * 8;
            unsigned af[4][4], bf[4][2];
            #pragma unroll
            for (int mt = 0; mt < 4; mt++) {
                const int m = wm + mt * 16;
                af[mt][0] = __float_as_uint(As[buf][m + gid    ][kb + tig]);
                af[mt][1] = __float_as_uint(As[buf][m + gid + 8][kb + tig]);
                af[mt][2] = __float_as_uint(As[buf][m + gid    ][kb + tig + 4]);
                af[mt][3] = __float_as_uint(As[buf][m + gid + 8][kb + tig + 4]);
            }
            #pragma unroll
            for (int nt = 0; nt < 4; nt++) {
                const int n = wn + nt * 8;
                bf[nt][0] = __float_as_uint(Bs[buf][kb + tig    ][n + gid]);
                bf[nt][1] = __float_as_uint(Bs[buf][kb + tig + 4][n + gid]);
            }
            #pragma unroll
            for (int mt = 0; mt < 4; mt++)
                #pragma unroll
                for (int nt = 0; nt < 4; nt++) {
                    asm volatile(
                        "mma.sync.aligned.m16n8k8.row.col.f32.tf32.tf32.f32 "
                        "{%0,%1,%2,%3}, {%4,%5,%6,%7}, {%8,%9}, {%0,%1,%2,%3};"
                        : "+f"(acc[mt][nt][0]), "+f"(acc[mt][nt][1]),
                          "+f"(acc[mt][nt][2]), "+f"(acc[mt][nt][3])
                        : "r"(af[mt][0]), "r"(af[mt][1]), "r"(af[mt][2]), "r"(af[mt][3]),
                          "r"(bf[nt][0]), "r"(bf[nt][1]));
                }
        }
        __syncthreads();
    }

    #pragma unroll
    for (int mt = 0; mt < 4; mt++) {
        #pragma unroll
        for (int nt = 0; nt < 4; nt++) {
            const int r0 = blockM + wm + mt * 16 + gid;
            const int c0 = blockN + wn + nt * 8 + 2 * tig;
            #pragma unroll
            for (int half = 0; half < 2; half++) {
                const int r = r0 + half * 8;
                #pragma unroll
                for (int j = 0; j < 2; j++) {
                    const int c = c0 + j;
                    float v = acc[mt][nt][half * 2 + j];
                    if (EPI == 2) {
                        v += res[(size_t)r * ldres + c];
                    } else if (EPI == 3) {
                        v += bias[c];
                        v = 0.5f * v * (1.f + erff(v * 0.70710678118654752f));
                        v = roundtf(v);   // feeds next tf32 GEMM as A operand
                    } else if (EPI == 4) {
                        v += bias[c];
                    }
                    C[(size_t)r * ldc + c] = v;
                }
            }
        }
    }
}

// ---------------------------------------------------------------------------
// fp32 tiled GEMM with optional split-K via blockIdx.z (kc = K per split).
// EPI: 0=store(partial)  1=bias+softplus
// ---------------------------------------------------------------------------
#define BM 128
#define BN 128
#define BK 8

template<int EPI>
__global__ __launch_bounds__(256) void sgemm_k(
    const float* __restrict__ A, const float* __restrict__ B, float* __restrict__ C,
    int M, int Ncol, int kc, int lda, int ldb, int ldc,
    const float* __restrict__ bias)
{
    A += (size_t)blockIdx.z * kc;
    B += (size_t)blockIdx.z * kc * ldb;
    C += (size_t)blockIdx.z * (size_t)M * ldc;

    __shared__ float As[BK][BM + 4];
    __shared__ float Bs[BK][BN + 4];

    const int tid = threadIdx.x;
    const int tx  = tid & 15;
    const int ty  = tid >> 4;
    const int aRow = tid >> 1;
    const int aCol = (tid & 1) << 2;
    const int bRow = tid >> 5;
    const int bCol = (tid & 31) << 2;
    const int blockM = blockIdx.y * BM;
    const int blockN = blockIdx.x * BN;

    float acc[2][2][4][4];
    #pragma unroll
    for (int p = 0; p < 2; p++)
        #pragma unroll
        for (int q = 0; q < 2; q++)
            #pragma unroll
            for (int i = 0; i < 4; i++)
                #pragma unroll
                for (int j = 0; j < 4; j++) acc[p][q][i][j] = 0.f;

    const float* Ap = A + (size_t)(blockM + aRow) * lda + aCol;
    const float* Bp = B + (size_t)bRow * ldb + blockN + bCol;
    const bool bIn = (blockN + bCol) < Ncol;

    for (int k0 = 0; k0 < kc; k0 += BK) {
        float4 av = *reinterpret_cast<const float4*>(Ap + k0);
        float4 bv = make_float4(0.f, 0.f, 0.f, 0.f);
        if (bIn) bv = *reinterpret_cast<const float4*>(Bp + (size_t)k0 * ldb);
        As[aCol + 0][aRow] = av.x;
        As[aCol + 1][aRow] = av.y;
        As[aCol + 2][aRow] = av.z;
        As[aCol + 3][aRow] = av.w;
        *reinterpret_cast<float4*>(&Bs[bRow][bCol]) = bv;
        __syncthreads();

        #pragma unroll
        for (int kk = 0; kk < BK; kk++) {
            float ar[2][4], br[2][4];
            #pragma unroll
            for (int p = 0; p < 2; p++) {
                float4 t = *reinterpret_cast<const float4*>(&As[kk][p * 64 + ty * 4]);
                ar[p][0] = t.x; ar[p][1] = t.y; ar[p][2] = t.z; ar[p][3] = t.w;
                float4 u = *reinterpret_cast<const float4*>(&Bs[kk][p * 64 + tx * 4]);
                br[p][0] = u.x; br[p][1] = u.y; br[p][2] = u.z; br[p][3] = u.w;
            }
            #pragma unroll
            for (int p = 0; p < 2; p++)
                #pragma unroll
                for (int q = 0; q < 2; q++)
                    #pragma unroll
                    for (int i = 0; i < 4; i++)
                        #pragma unroll
                        for (int j = 0; j < 4; j++)
                            acc[p][q][i][j] = fmaf(ar[p][i], br[q][j], acc[p][q][i][j]);
        }
        __syncthreads();
    }

    #pragma unroll
    for (int p = 0; p < 2; p++) {
        #pragma unroll
        for (int i = 0; i < 4; i++) {
            const int r = blockM + p * 64 + ty * 4 + i;
            #pragma unroll
            for (int q = 0; q < 2; q++) {
                const int cbase = blockN + q * 64 + tx * 4;
                if (cbase < Ncol) {
                    #pragma unroll
                    for (int j = 0; j < 4; j++) {
                        const int c = cbase + j;
                        float v = acc[p][q][i][j];
                        if (EPI == 1) {
                            v += bias[c];
                            v = (v > 20.f) ? v : log1pf(expf(v));
                        }
                        C[(size_t)r * ldc + c] = v;
                    }
                }
            }
        }
    }
}

// ---------------------------------------------------------------------------
// Sum the 8 split-K partials -> g_dtBC. Fixed order => deterministic.
// ---------------------------------------------------------------------------
__global__ void reduce8_k()
{
    const int i = blockIdx.x * blockDim.x + threadIdx.x;    // float4 index
    const int n4 = ROWS * PROJC / 4;
    if (i < n4) {
        const float4* p = reinterpret_cast<const float4*>(g_xpart);
        float4 s = p[i];
        #pragma unroll
        for (int k = 1; k < KSPLIT; k++) {
            float4 v = p[(size_t)k * n4 + i];
            s.x += v.x; s.y += v.y; s.z += v.z; s.w += v.w;
        }
        reinterpret_cast<float4*>(g_dtBC)[i] = s;
    }
}

// ---------------------------------------------------------------------------
// Depthwise causal conv1d (K=4) + silu
// ---------------------------------------------------------------------------
__global__ __launch_bounds__(256) void conv_silu_k(
    const float* __restrict__ cw, const float* __restrict__ cb)
{
    const int idx = blockIdx.x * blockDim.x + threadIdx.x;
    if (idx >= ROWS * EDIM) return;
    const int e   = idx & (EDIM - 1);
    const int row = idx >> 11;
    const int l   = row & (SEQ - 1);

    const float w0 = cw[e * 4 + 0], w1 = cw[e * 4 + 1];
    const float w2 = cw[e * 4 + 2], w3 = cw[e * 4 + 3];
    const float* base = g_xz + (size_t)row * (2 * EDIM) + e;

    float acc = fmaf(w3, base[0], cb[e]);
    if (l >= 1) acc = fmaf(w2, base[-(ptrdiff_t)(2 * EDIM)], acc);
    if (l >= 2) acc = fmaf(w1, base[-(ptrdiff_t)(4 * EDIM)], acc);
    if (l >= 3) acc = fmaf(w0, base[-(ptrdiff_t)(6 * EDIM)], acc);
    acc = acc / (1.f + expf(-acc));
    g_xc[idx] = acc;
}

__global__ void prep_A_k(const float* __restrict__ A_log)
{
    const int i = blockIdx.x * blockDim.x + threadIdx.x;
    if (i < EDIM * NSTATE) g_A[i] = -expf(A_log[i]);
}

// ---------------------------------------------------------------------------
// Selective scan, smem-staged. Block = 16 consecutive e of one batch,
// 256 thr = 16 groups x 16 state-lanes. l processed in chunks of 64 with
// coalesced tile loads ([64 l][16 e], 64B rows) and coalesced y flush.
// y written tf32-rounded (consumed by W_out tf32 GEMM).
// ---------------------------------------------------------------------------
#define SC_CH 64

__global__ __launch_bounds__(256) void scan_k(const float* __restrict__ Dp)
{
    __shared__ float sdt[SC_CH][16], sxc[SC_CH][16], szv[SC_CH][16];
    __shared__ float sB [SC_CH][16], sC [SC_CH][16], sy [SC_CH][16];

    const int tid = threadIdx.x;
    const int g   = tid >> 4;
    const int n   = tid & 15;
    const int blk = blockIdx.x;             // 0..511
    const int b   = blk >> 7;               // 128 blocks per batch
    const int e0  = (blk & 127) * 16;
    const int eg  = e0 + g;                 // this group's channel

    const float An = g_A[eg * NSTATE + n];
    const float De = Dp[eg];
    float h = 0.f;

    const int row0 = b * SEQ;
    const int lcol = tid & 15;              // e-offset for tile loads
    const int lrow = tid >> 4;              // l-offset base for tile loads

    for (int l0 = 0; l0 < SEQ; l0 += SC_CH) {
        // ---- load tiles (each thread: 4 rows of its column) ----
        #pragma unroll
        for (int j = 0; j < 4; j++) {
            const int li = lrow + j * 16;
            const size_t r = (size_t)(row0 + l0 + li);
            sdt[li][lcol] = g_dt  [r * EDIM + e0 + lcol];
            sxc[li][lcol] = g_xc  [r * EDIM + e0 + lcol];
            szv[li][lcol] = g_xz  [r * (2 * EDIM) + EDIM + e0 + lcol];
            sB [li][lcol] = g_dtBC[r * PROJC + DTR + lcol];
            sC [li][lcol] = g_dtBC[r * PROJC + DTR + NSTATE + lcol];
        }
        __syncthreads();

        // ---- serial scan over the chunk ----
        #pragma unroll 2
        for (int i = 0; i < SC_CH; i++) {
            const float du = sdt[i][g];
            const float u  = sxc[i][g];
            const float Bn = sB[i][n];
            const float Cn = sC[i][n];

            const float a = __expf(du * An);
            h = fmaf(a, h, du * u * Bn);

            float p = h * Cn;
            p += __shfl_xor_sync(0xffffffffu, p, 1);
            p += __shfl_xor_sync(0xffffffffu, p, 2);
            p += __shfl_xor_sync(0xffffffffu, p, 4);
            p += __shfl_xor_sync(0xffffffffu, p, 8);

            if (n == 0) {
                const float z  = szv[i][g];
                const float sz = z / (1.f + __expf(-z));
                sy[i][g] = roundtf(fmaf(u, De, p) * sz);
            }
        }
        __syncthreads();

        // ---- flush y tile (coalesced) ----
        #pragma unroll
        for (int j = 0; j < 4; j++) {
            const int li = lrow + j * 16;
            const size_t r = (size_t)(row0 + l0 + li);
            g_y[r * EDIM + e0 + lcol] = sy[li][lcol];
        }
        __syncthreads();
    }
}

// ---------------------------------------------------------------------------
// LayerNorm over DIM=1024 -> g_hn (tf32-rounded; consumed by W1 tf32 GEMM)
// ---------------------------------------------------------------------------
__global__ __launch_bounds__(256) void ln_k(
    const float* __restrict__ w, const float* __restrict__ b)
{
    const int row = blockIdx.x;
    const float4 v = reinterpret_cast<const float4*>(g_h + (size_t)row * DIM)[threadIdx.x];

    float s  = v.x + v.y + v.z + v.w;
    float ss = v.x * v.x + v.y * v.y + v.z * v.z + v.w * v.w;
    #pragma unroll
    for (int o = 16; o > 0; o >>= 1) {
        s  += __shfl_xor_sync(0xffffffffu, s,  o);
        ss += __shfl_xor_sync(0xffffffffu, ss, o);
    }
    __shared__ float sh_s[8], sh_ss[8];
    const int warp = threadIdx.x >> 5, lane = threadIdx.x & 31;
    if (lane == 0) { sh_s[warp] = s; sh_ss[warp] = ss; }
    __syncthreads();
    if (warp == 0) {
        s  = (lane < 8) ? sh_s[lane]  : 0.f;
        ss = (lane < 8) ? sh_ss[lane] : 0.f;
        #pragma unroll
        for (int o = 4; o > 0; o >>= 1) {
            s  += __shfl_xor_sync(0xffffffffu, s,  o);
            ss += __shfl_xor_sync(0xffffffffu, ss, o);
        }
        if (lane == 0) { sh_s[0] = s; sh_ss[0] = ss; }
    }
    __syncthreads();
    const float mean = sh_s[0] * (1.f / DIM);
    const float var  = sh_ss[0] * (1.f / DIM) - mean * mean;
    const float inv  = rsqrtf(var + 1e-5f);

    const float4 wv = reinterpret_cast<const float4*>(w)[threadIdx.x];
    const float4 bv = reinterpret_cast<const float4*>(b)[threadIdx.x];
    float4 o;
    o.x = roundtf((v.x - mean) * inv * wv.x + bv.x);
    o.y = roundtf((v.y - mean) * inv * wv.y + bv.y);
    o.z = roundtf((v.z - mean) * inv * wv.z + bv.z);
    o.w = roundtf((v.w - mean) * inv * wv.w + bv.w);
    reinterpret_cast<float4*>(g_hn + (size_t)row * DIM)[threadIdx.x] = o;
}

// ---------------------------------------------------------------------------
// Launch
// ---------------------------------------------------------------------------
extern "C" void kernel_launch(void* const* d_in, const int* in_sizes, int n_in,
                              void* d_out, int out_size)
{
    const float* x       = (const float*)d_in[0];
    const float* W_in    = (const float*)d_in[1];
    const float* conv_w  = (const float*)d_in[2];
    const float* conv_b  = (const float*)d_in[3];
    const float* W_xproj = (const float*)d_in[4];
    const float* W_dt    = (const float*)d_in[5];
    const float* b_dt    = (const float*)d_in[6];
    const float* A_log   = (const float*)d_in[7];
    const float* D_param = (const float*)d_in[8];
    const float* W_out   = (const float*)d_in[9];
    const float* ln_w    = (const float*)d_in[10];
    const float* ln_b    = (const float*)d_in[11];
    const float* W1      = (const float*)d_in[12];
    const float* b1      = (const float*)d_in[13];
    const float* W2      = (const float*)d_in[14];
    const float* b2      = (const float*)d_in[15];
    float* out = (float*)d_out;

    float *xz, *xc, *dtbc, *dtb, *yb, *hb, *hnb, *midb, *xpart;
    float *xr, *Winr, *W1r, *W2r, *Woutr;
    cudaGetSymbolAddress((void**)&xz,    g_xz);
    cudaGetSymbolAddress((void**)&xc,    g_xc);
    cudaGetSymbolAddress((void**)&dtbc,  g_dtBC);
    cudaGetSymbolAddress((void**)&dtb,   g_dt);
    cudaGetSymbolAddress((void**)&yb,    g_y);
    cudaGetSymbolAddress((void**)&hb,    g_h);
    cudaGetSymbolAddress((void**)&hnb,   g_hn);
    cudaGetSymbolAddress((void**)&midb,  g_mid);
    cudaGetSymbolAddress((void**)&xpart, g_xpart);
    cudaGetSymbolAddress((void**)&xr,    g_xr);
    cudaGetSymbolAddress((void**)&Winr,  g_Winr);
    cudaGetSymbolAddress((void**)&W1r,   g_W1r);
    cudaGetSymbolAddress((void**)&W2r,   g_W2r);
    cudaGetSymbolAddress((void**)&Woutr, g_Woutr);

    // 0) prep: A = -exp(A_log); tf32 round-copies of tensor-core operands
    prep_A_k<<<(EDIM * NSTATE + 255) / 256, 256>>>(A_log);
    round_copy_k<<<(ROWS * DIM / 4 + 255) / 256, 256>>>(x, xr, ROWS * DIM / 4);
    round_copy_k<<<(DIM * 2 * EDIM / 4 + 255) / 256, 256>>>(W_in, Winr, DIM * 2 * EDIM / 4);
    round_copy_k<<<(DIM * HDIM / 4 + 255) / 256, 256>>>(W1, W1r, DIM * HDIM / 4);
    round_copy_k<<<(HDIM * DIM / 4 + 255) / 256, 256>>>(W2, W2r, HDIM * DIM / 4);
    round_copy_k<<<(EDIM * DIM / 4 + 255) / 256, 256>>>(W_out, Woutr, EDIM * DIM / 4);

    // 1) xz = x @ W_in   (8192x4096, K=1024) [tf32, fp32 out]
    tgemm_k<0><<<dim3(4096 / TBN, ROWS / TBM), 256>>>(
        xr, Winr, xz, DIM, DIM, 4096, 4096, nullptr, nullptr, 0);

    // 2) depthwise conv + silu
    conv_silu_k<<<(ROWS * EDIM + 255) / 256, 256>>>(conv_w, conv_b);

    // 3) xproj split-K (8192x96, K=2048 in 8x256) + reduce
    sgemm_k<0><<<dim3(1, ROWS / BM, KSPLIT), 256>>>(
        xc, W_xproj, xpart, ROWS, PROJC, EDIM / KSPLIT, EDIM, PROJC, PROJC, nullptr);
    reduce8_k<<<(ROWS * PROJC / 4 + 255) / 256, 256>>>();

    // 4) dt = softplus(proj[:, :64] @ W_dt + b_dt)   (8192x2048, K=64) [fp32]
    sgemm_k<1><<<dim3(EDIM / BN, ROWS / BM, 1), 256>>>(
        dtbc, W_dt, dtb, ROWS, EDIM, DTR, PROJC, EDIM, EDIM, b_dt);

    // 5) selective scan (fused D-term + z gate, tf32-rounded y)
    scan_k<<<512, 256>>>(D_param);

    // 6) h = x + y @ W_out   (8192x1024, K=2048) [tf32 + fp32 residual]
    tgemm_k<2><<<dim3(DIM / TBN, ROWS / TBM), 256>>>(
        yb, Woutr, hb, EDIM, EDIM, DIM, DIM, nullptr, x, DIM);

    // 7) layernorm -> hn (tf32-rounded)
    ln_k<<<ROWS, 256>>>(ln_w, ln_b);

    // 8) mid = gelu(hn @ W1 + b1)   (8192x4096, K=1024) [tf32, rounded out]
    tgemm_k<3><<<dim3(HDIM / TBN, ROWS / TBM), 256>>>(
        hnb, W1r, midb, DIM, DIM, HDIM, HDIM, b1, nullptr, 0);

    // 9) out = mid @ W2 + b2   (8192x1024, K=4096) [tf32]
    tgemm_k<4><<<dim3(DIM / TBN, ROWS / TBM), 256>>>(
        midb, W2r, out, HDIM, HDIM, DIM, DIM, b2, nullptr, 0);
}